// round 16
// baseline (speedup 1.0000x reference)
#include <cuda_runtime.h>
#include <cuda_bf16.h>
#include <stdint.h>

// Problem constants
#define BATCH   64
#define IN_DIM  1024
#define OUT_DIM 1024
#define STEPS   100
#define TPROJ   99
#define MTOT    (TPROJ * BATCH)   // 6336
#define NEUR    (BATCH * OUT_DIM) // 65536

// NUMERICS CONTRACT (verified bitwise rel_err==0.0 in R13/R14):
//   proj[m][o] = fadd( P0, P1 ), P0 = k-ascending fp32 chain over [0,520),
//   P1 over [520,1024). x in {0,1}: zero steps are exact no-ops, one steps
//   are exact fadds -> sparse ascending gather-sum is bitwise identical.
#define KSPLIT  520
#define LMAX    320               // max active k per row (mean 205, +9 sigma)

// Scratch (device globals: allocation-free rule)
__device__ float    g_xT[MTOT * IN_DIM];
__device__ float    g_WT[IN_DIM * OUT_DIM];   // WT[k][o]
__device__ float    g_proj[MTOT * OUT_DIM];
__device__ uint16_t g_klist[(size_t)MTOT * LMAX];
__device__ int      g_kcnt[MTOT];
__device__ int      g_ksplit[MTOT];

// ---------------------------------------------------------------------------
// Kernel 1: transpose x[b][i][t] -> xT[(t*64+b)][i]
// ---------------------------------------------------------------------------
__global__ void transpose_x_kernel(const float* __restrict__ x) {
    __shared__ float tile[32][33];
    const int b  = blockIdx.z;
    const int i0 = blockIdx.y * 32;
    const int t0 = blockIdx.x * 32;

    #pragma unroll
    for (int r = threadIdx.y; r < 32; r += 8) {
        const int i = i0 + r;
        const int t = t0 + threadIdx.x;
        float v = 0.0f;
        if (t < TPROJ) v = x[(b * IN_DIM + i) * STEPS + t];
        tile[r][threadIdx.x] = v;
    }
    __syncthreads();
    #pragma unroll
    for (int r = threadIdx.y; r < 32; r += 8) {
        const int t = t0 + r;
        const int i = i0 + threadIdx.x;
        if (t < TPROJ)
            g_xT[(t * BATCH + b) * IN_DIM + i] = tile[threadIdx.x][r];
    }
}

// ---------------------------------------------------------------------------
// Kernel 2: transpose W[o][k] -> WT[k][o]
// ---------------------------------------------------------------------------
__global__ void wt_kernel(const float* __restrict__ W) {
    __shared__ float tile[32][33];
    const int k0 = blockIdx.x * 32;
    const int o0 = blockIdx.y * 32;

    #pragma unroll
    for (int r = threadIdx.y; r < 32; r += 8)
        tile[r][threadIdx.x] = W[(o0 + r) * IN_DIM + k0 + threadIdx.x];
    __syncthreads();
    #pragma unroll
    for (int r = threadIdx.y; r < 32; r += 8)
        g_WT[(k0 + r) * OUT_DIM + o0 + threadIdx.x] = tile[threadIdx.x][r];
}

// ---------------------------------------------------------------------------
// Kernel 3: build per-row active-k lists (ascending) + split at k=520.
// One warp per m-row; ballot/popc compaction preserves ascending order.
// ---------------------------------------------------------------------------
__global__ void build_lists_kernel() {
    const int wid  = (blockIdx.x * blockDim.x + threadIdx.x) >> 5;
    const int lane = threadIdx.x & 31;
    if (wid >= MTOT) return;

    const float* row = g_xT + (size_t)wid * IN_DIM;
    uint16_t* lst = g_klist + (size_t)wid * LMAX;
    int cnt = 0, split = 0;

    #pragma unroll
    for (int c = 0; c < 32; ++c) {
        const float v = row[c * 32 + lane];
        const bool act = (v > 0.5f);
        const unsigned mask = __ballot_sync(0xffffffffu, act);
        if (act) {
            const int pos = cnt + __popc(mask & ((1u << lane) - 1u));
            lst[pos] = (uint16_t)(c * 32 + lane);
        }
        cnt += __popc(mask);
        if (c == 15) split = cnt;                       // k < 512
        if (c == 16) split += __popc(mask & 0xFFu);     // k = 512..519
    }
    if (lane == 0) { g_kcnt[wid] = cnt; g_ksplit[wid] = split; }
}

// ---------------------------------------------------------------------------
// Kernel 4: sparse gather-sum "GEMM".
// CTA = (o-tile of 32 columns) x (m-chunk, 37 chunks). 1184 = 148*8 CTAs.
// smem: WT strip [1024 k][32 o] = 128KB (dynamic). Warp = one m, lane = one o.
// Inner loop: idx broadcast + 128B conflict-free LDS row + serial __fadd_rn.
// P0/P1 fold: list iterated in two segments split at first k>=520.
// ---------------------------------------------------------------------------
#define MCHUNKS 37
#define GTHREADS 512

extern __shared__ float sWT[];   // [1024][32]

__global__ __launch_bounds__(GTHREADS, 1)
void gather_kernel() {
    const int o0  = (blockIdx.x & 31) * 32;
    const int mc  = blockIdx.x >> 5;             // 0..36
    const int mlo = (MTOT * mc) / MCHUNKS;
    const int mhi = (MTOT * (mc + 1)) / MCHUNKS;
    const int tid = threadIdx.x;
    const int lane = tid & 31;
    const int wid  = tid >> 5;                   // 0..15

    // stage WT strip: 1024 rows x 32 floats (128B rows)
    for (int i = tid; i < IN_DIM * 8; i += GTHREADS) {
        const int k = i >> 3, f = i & 7;
        *(float4*)&sWT[k * 32 + f * 4] =
            *(const float4*)&g_WT[(size_t)k * OUT_DIM + o0 + f * 4];
    }
    __syncthreads();

    for (int m = mlo + wid; m < mhi; m += GTHREADS / 32) {
        const uint16_t* lst = g_klist + (size_t)m * LMAX;
        const int cnt   = g_kcnt[m];
        const int split = g_ksplit[m];

        float a0 = 0.0f, a1 = 0.0f;
        int j = 0;
        #pragma unroll 4
        for (; j < split; ++j)
            a0 = __fadd_rn(a0, sWT[(int)lst[j] * 32 + lane]);
        #pragma unroll 4
        for (; j < cnt; ++j)
            a1 = __fadd_rn(a1, sWT[(int)lst[j] * 32 + lane]);

        g_proj[(size_t)m * OUT_DIM + o0 + lane] = __fadd_rn(a0, a1);
    }
}

// ---------------------------------------------------------------------------
// Kernel 5: LIF scan, warp-transposed coalesced output (bitwise contract:
// separate __fmul_rn/__fadd_rn, select-reset; verified R13/R14).
// ---------------------------------------------------------------------------
__global__ void lif_scan_kernel(float* __restrict__ out) {
    const int lane = threadIdx.x & 31;
    const int warp = (blockIdx.x * blockDim.x + threadIdx.x) >> 5;
    const int n0   = warp * 32;
    const int nid  = n0 + lane;

    const float a_m = 0.95f;
    const float b_m = 0.05f;
    const float a_s = 0.8f;

    float V = 0.0f, I = 0.0f;
    int t = 0;

    #pragma unroll
    for (int c = 0; c < 4; ++c) {
        const int jlo   = (c == 0) ? 1 : 0;
        const int ncols = (c == 3) ? 4 : 32;
        unsigned mask = 0u;

        for (int j = jlo; j < ncols; ++j) {
            const float p  = g_proj[(size_t)t * NEUR + nid];
            const float Vn = __fadd_rn(__fmul_rn(a_m, V), __fmul_rn(b_m, I));
            I = __fadd_rn(__fmul_rn(a_s, I), p);
            const bool sp = (Vn > 1.0f);
            mask |= (sp ? 1u : 0u) << j;
            V = sp ? 0.0f : Vn;
            ++t;
        }

        const int cbase = c * 32;
        #pragma unroll
        for (int r = 0; r < 32; ++r) {
            const unsigned m = __shfl_sync(0xffffffffu, mask, r);
            if (lane < ncols)
                out[(size_t)(n0 + r) * STEPS + cbase + lane] =
                    ((m >> lane) & 1u) ? 1.0f : 0.0f;
        }
    }
}

// ---------------------------------------------------------------------------
extern "C" void kernel_launch(void* const* d_in, const int* in_sizes, int n_in,
                              void* d_out, int out_size) {
    const float* x = (const float*)d_in[0];
    const float* W = (const float*)d_in[1];
    if (in_sizes[0] == OUT_DIM * IN_DIM && in_sizes[1] == BATCH * IN_DIM * STEPS) {
        x = (const float*)d_in[1];
        W = (const float*)d_in[0];
    }
    float* out = (float*)d_out;

    static bool attr_set = false;
    if (!attr_set) {
        cudaFuncSetAttribute(gather_kernel,
                             cudaFuncAttributeMaxDynamicSharedMemorySize,
                             IN_DIM * 32 * (int)sizeof(float));
        attr_set = true;
    }

    {   // x transpose
        dim3 grid(4, IN_DIM / 32, BATCH);
        dim3 block(32, 8);
        transpose_x_kernel<<<grid, block>>>(x);
    }
    {   // W transpose
        dim3 grid(IN_DIM / 32, OUT_DIM / 32);
        dim3 block(32, 8);
        wt_kernel<<<grid, block>>>(W);
    }
    {   // active-k lists (one warp per row)
        const int warps_per_block = 8;
        const int blocks = (MTOT + warps_per_block - 1) / warps_per_block;
        build_lists_kernel<<<blocks, warps_per_block * 32>>>();
    }
    {   // sparse gather "GEMM"
        gather_kernel<<<32 * MCHUNKS, GTHREADS,
                        IN_DIM * 32 * (int)sizeof(float)>>>();
    }
    {   // LIF scan
        const int threads = 256;
        lif_scan_kernel<<<NEUR / threads, threads>>>(out);
    }
}